// round 4
// baseline (speedup 1.0000x reference)
#include <cuda_runtime.h>

#define NPTS 1024
#define HID  256
#define XD   128

// ---------------- pair kernel tiling ----------------
#define TJ   64
#define TI   64
#define SWID 260         // row stride (floats); mult of 4 (16B align), 260%32=4 -> conflict-free
#define SMEM_BYTES (((TJ + TI) * SWID + 256) * 4)

// ---------------- prologue tiling ----------------
#define PROWS 32         // rows per block
#define PCOLS 64         // cols per block
#define PW    132        // padded k-stride (floats), mult of 4

// ---- device scratch ----
__device__ float g_xp [NPTS * HID];
__device__ float g_ypb[NPTS * HID];
__device__ float g_pexp [256];
__device__ float g_pdiag[256];

// packed f32x2 relu-dot: acc += relu(a + c) * w  (2 elems)
#define RELU_DOT(ACC, A, C, W)                         \
  asm("{\n\t"                                          \
      ".reg .b64 zz, rr;\n\t"                          \
      ".reg .f32 zl, zh, rl, rh;\n\t"                  \
      "add.rn.f32x2 zz, %1, %2;\n\t"                   \
      "mov.b64 {zl, zh}, zz;\n\t"                      \
      "max.f32 rl, zl, 0f00000000;\n\t"                \
      "max.f32 rh, zh, 0f00000000;\n\t"                \
      "mov.b64 rr, {rl, rh};\n\t"                      \
      "fma.rn.f32x2 %0, rr, %3, %0;\n\t"               \
      "}" : "+l"(ACC) : "l"(A), "l"(C), "l"(W))

#define FMA2(ACC, A, W) \
  asm("fma.rn.f32x2 %0, %1, %2, %0;" : "+l"(ACC) : "l"(A), "l"(W))

// ---------------- prologue: xp = x @ W1[:128], ypb = y @ W1[128:] + b1 ----------------
// grid (32 row-blocks, 4 col-blocks, 2 which); block 128 threads; microtile 4r x 4c,
// k packed into f32x2 accumulators (sum halves at the end).
__global__ void __launch_bounds__(128) prologue_kernel(
    const float* __restrict__ x, const float* __restrict__ y,
    const float* __restrict__ W1, const float* __restrict__ b1)
{
  __shared__ float sx[PROWS * PW];    // [row][k]
  __shared__ float swt[PCOLS * PW];   // [col][k]  (W transposed)

  const int which = blockIdx.z;
  const float* src = which ? y : x;
  const int r0 = blockIdx.x * PROWS;
  const int c0 = blockIdx.y * PCOLS;
  const int tid = threadIdx.x;

  // x tile: 32 rows x 128 k (contiguous)
  for (int t = tid; t < PROWS * (XD / 4); t += 128) {
    const int r = t >> 5, c4 = t & 31;
    *reinterpret_cast<float4*>(&sx[r * PW + c4 * 4]) =
        *reinterpret_cast<const float4*>(&src[(r0 + r) * XD + c4 * 4]);
  }
  // W tile transposed: swt[c][k] = W1[base + k*HID + c0 + c]
  const float* Wb = W1 + (which ? (XD * HID) : 0);
  for (int t = tid; t < PCOLS * XD; t += 128) {
    const int k = t >> 6, c = t & 63;
    swt[c * PW + k] = Wb[k * HID + c0 + c];
  }
  __syncthreads();

  const int tc = tid & 15;   // col group (0..15), cols tc + 16*cc
  const int tr = tid >> 4;   // row group (0..7),  rows tr + 8*rr

  unsigned long long acc[4][4];
#pragma unroll
  for (int rr = 0; rr < 4; rr++)
#pragma unroll
    for (int cc = 0; cc < 4; cc++) acc[rr][cc] = 0ull;

#pragma unroll 4
  for (int k = 0; k < XD; k += 4) {
    ulonglong2 av[4], wv[4];
#pragma unroll
    for (int rr = 0; rr < 4; rr++)
      av[rr] = *reinterpret_cast<const ulonglong2*>(&sx[(tr + 8 * rr) * PW + k]);
#pragma unroll
    for (int cc = 0; cc < 4; cc++)
      wv[cc] = *reinterpret_cast<const ulonglong2*>(&swt[(tc + 16 * cc) * PW + k]);
#pragma unroll
    for (int rr = 0; rr < 4; rr++)
#pragma unroll
      for (int cc = 0; cc < 4; cc++) {
        FMA2(acc[rr][cc], av[rr].x, wv[cc].x);
        FMA2(acc[rr][cc], av[rr].y, wv[cc].y);
      }
  }

  float* dst = which ? g_ypb : g_xp;
#pragma unroll
  for (int rr = 0; rr < 4; rr++)
#pragma unroll
    for (int cc = 0; cc < 4; cc++) {
      union { unsigned long long u; float2 f; } uu;
      uu.u = acc[rr][cc];
      const int col = c0 + tc + 16 * cc;
      float v = uu.f.x + uu.f.y;
      if (which) v += b1[col];
      dst[(r0 + tr + 8 * rr) * HID + col] = v;
    }
}

// ---------------- main pairwise kernel ----------------
// grid (16 j, 16 i); block 256 threads; microtile 4j x 4i (strided 16)
__global__ void __launch_bounds__(256, 1) pair_kernel(
    const float* __restrict__ W2, const float* __restrict__ b2)
{
  extern __shared__ float sm[];
  float* sa = sm;                       // TJ rows of xp
  float* sc = sm + TJ * SWID;           // TI rows of ypb
  float* sw = sm + (TJ + TI) * SWID;    // W2 (reused for reductions)

  const int tid = threadIdx.x;
  const int bj = blockIdx.x, bi = blockIdx.y;
  const int jbase = bj * TJ, ibase = bi * TI;

  {
    const float4* src = reinterpret_cast<const float4*>(&g_xp[jbase * HID]);
    for (int t = tid; t < TJ * (HID / 4); t += 256) {
      const int r = t >> 6, c4 = t & 63;
      *reinterpret_cast<float4*>(&sa[r * SWID + c4 * 4]) = src[r * 64 + c4];
    }
  }
  {
    const float4* src = reinterpret_cast<const float4*>(&g_ypb[ibase * HID]);
    for (int t = tid; t < TI * (HID / 4); t += 256) {
      const int r = t >> 6, c4 = t & 63;
      *reinterpret_cast<float4*>(&sc[r * SWID + c4 * 4]) = src[r * 64 + c4];
    }
  }
  sw[tid] = W2[tid];
  __syncthreads();

  const int tx = tid & 15;    // j
  const int ty = tid >> 4;    // i (0..15)

  unsigned long long acc[16];
#pragma unroll
  for (int p = 0; p < 16; p++) acc[p] = 0ull;

#pragma unroll 2
  for (int k = 0; k < HID; k += 4) {
    const ulonglong2 wv = *reinterpret_cast<const ulonglong2*>(&sw[k]);
    ulonglong2 av[4], cv[4];
#pragma unroll
    for (int jj = 0; jj < 4; jj++)
      av[jj] = *reinterpret_cast<const ulonglong2*>(&sa[(tx + 16 * jj) * SWID + k]);
#pragma unroll
    for (int ii = 0; ii < 4; ii++)
      cv[ii] = *reinterpret_cast<const ulonglong2*>(&sc[(ty + 16 * ii) * SWID + k]);
#pragma unroll
    for (int ii = 0; ii < 4; ii++)
#pragma unroll
      for (int jj = 0; jj < 4; jj++) {
        RELU_DOT(acc[ii * 4 + jj], av[jj].x, cv[ii].x, wv.x);
        RELU_DOT(acc[ii * 4 + jj], av[jj].y, cv[ii].y, wv.y);
      }
  }

  const float b2v = __ldg(b2);
  float eacc = 0.0f, dacc = 0.0f;
#pragma unroll
  for (int ii = 0; ii < 4; ii++)
#pragma unroll
    for (int jj = 0; jj < 4; jj++) {
      union { unsigned long long u; float2 f; } uu;
      uu.u = acc[ii * 4 + jj];
      const float t = uu.f.x + uu.f.y + b2v;
      eacc += __expf(t - 1.0f);
      const int gi = ibase + ty + 16 * ii;
      const int gj = jbase + tx + 16 * jj;
      if (gi == gj) dacc += t;
    }

  __syncthreads();
  sw[tid] = eacc;
  __syncthreads();
  for (int s = 128; s > 0; s >>= 1) {
    if (tid < s) sw[tid] += sw[tid + s];
    __syncthreads();
  }
  if (tid == 0) g_pexp[bi * 16 + bj] = sw[0];
  __syncthreads();
  sw[tid] = dacc;
  __syncthreads();
  for (int s = 128; s > 0; s >>= 1) {
    if (tid < s) sw[tid] += sw[tid + s];
    __syncthreads();
  }
  if (tid == 0) g_pdiag[bi * 16 + bj] = sw[0];
}

// ---------------- finalize ----------------
__global__ void __launch_bounds__(256) finalize_kernel(float* out, int out_size)
{
  __shared__ float se[256];
  __shared__ float sd[256];
  const int tid = threadIdx.x;
  se[tid] = g_pexp[tid];
  sd[tid] = g_pdiag[tid];
  __syncthreads();
  for (int s = 128; s > 0; s >>= 1) {
    if (tid < s) { se[tid] += se[tid + s]; sd[tid] += sd[tid + s]; }
    __syncthreads();
  }
  if (tid == 0)
    out[0] = sd[0] * (1.0f / NPTS) - se[0] * (1.0f / ((float)NPTS * (float)NPTS));
  for (int t = tid; t < out_size; t += 256)
    if (t > 0) out[t] = 0.0f;
}

extern "C" void kernel_launch(void* const* d_in, const int* in_sizes, int n_in,
                              void* d_out, int out_size)
{
  const float* x  = (const float*)d_in[0];
  const float* y  = (const float*)d_in[1];
  const float* W1 = (const float*)d_in[2];
  const float* b1 = (const float*)d_in[3];
  const float* W2 = (const float*)d_in[4];
  const float* b2 = (const float*)d_in[5];

  cudaFuncSetAttribute(pair_kernel, cudaFuncAttributeMaxDynamicSharedMemorySize, SMEM_BYTES);

  prologue_kernel<<<dim3(32, 4, 2), 128>>>(x, y, W1, b1);
  pair_kernel<<<dim3(16, 16), 256, SMEM_BYTES>>>(W2, b2);
  finalize_kernel<<<1, 256>>>((float*)d_out, out_size);
}

// round 5
// speedup vs baseline: 1.6221x; 1.6221x over previous
#include <cuda_runtime.h>

#define NPTS 1024
#define HID  256
#define XD   128

// ---------------- pair kernel tiling (R1 config — known good) ----------------
#define TJ   64
#define TI   32
#define SWID 260
#define SMEM_BYTES (((TJ + TI) * SWID + 256) * 4)

// ---------------- prologue tiling ----------------
#define PR   16          // rows per block
#define PC   64          // cols per block
#define PAW  132         // a-row stride (floats)
#define PWW  68          // w-row stride (floats): 68%32=4, conflict-free staging + reads

// ---- device scratch ----
__device__ float g_xp [NPTS * HID];
__device__ float g_ypb[NPTS * HID];
__device__ float g_pexp [512];
__device__ float g_pdiag[512];

// packed f32x2 relu-dot: acc += relu(a + c) * w  (2 elems)
#define RELU_DOT(ACC, A, C, W)                         \
  asm("{\n\t"                                          \
      ".reg .b64 zz, rr;\n\t"                          \
      ".reg .f32 zl, zh, rl, rh;\n\t"                  \
      "add.rn.f32x2 zz, %1, %2;\n\t"                   \
      "mov.b64 {zl, zh}, zz;\n\t"                      \
      "max.f32 rl, zl, 0f00000000;\n\t"                \
      "max.f32 rh, zh, 0f00000000;\n\t"                \
      "mov.b64 rr, {rl, rh};\n\t"                      \
      "fma.rn.f32x2 %0, rr, %3, %0;\n\t"               \
      "}" : "+l"(ACC) : "l"(A), "l"(C), "l"(W))

// ---------------- prologue: xp = x @ W1[:128], ypb = y @ W1[128:] + b1 ----------------
// block 128 thr; tile 16r x 64c; microtile 2r x 4c; grid (64, 4, 2) = 512 blocks.
// W kept k-major in smem (no transpose). ~40 regs -> 4 CTAs/SM (16 warps).
__global__ void __launch_bounds__(128) prologue_kernel(
    const float* __restrict__ x, const float* __restrict__ y,
    const float* __restrict__ W1, const float* __restrict__ b1)
{
  __shared__ float sa[PR * PAW];     // [r][k]   16 x 132
  __shared__ float sw[XD * PWW];     // [k][c]  128 x 68

  const int which = blockIdx.z;
  const float* src = which ? y : x;
  const int r0 = blockIdx.x * PR;
  const int c0 = blockIdx.y * PC;
  const int tid = threadIdx.x;

  // stage a: 16 rows x 128 k  (512 float4, 128 thr -> 4 iters)
  for (int t = tid; t < PR * (XD / 4); t += 128) {
    const int r = t >> 5, k4 = t & 31;
    *reinterpret_cast<float4*>(&sa[r * PAW + k4 * 4]) =
        *reinterpret_cast<const float4*>(&src[(r0 + r) * XD + k4 * 4]);
  }
  // stage w: 128 k x 64 c (float4 along c; conflict-free with PWW=68)
  const float* Wb = W1 + (which ? (XD * HID) : 0) + c0;
  for (int t = tid; t < XD * (PC / 4); t += 128) {
    const int k = t >> 4, c4 = t & 15;
    *reinterpret_cast<float4*>(&sw[k * PWW + c4 * 4]) =
        *reinterpret_cast<const float4*>(&Wb[k * HID + c4 * 4]);
  }
  __syncthreads();

  const int tc = tid & 15;    // col group: cols 4*tc .. 4*tc+3
  const int tr = tid >> 4;    // row group: rows tr, tr+8

  float acc[2][4];
#pragma unroll
  for (int r = 0; r < 2; r++)
#pragma unroll
    for (int c = 0; c < 4; c++) acc[r][c] = 0.0f;

#pragma unroll 4
  for (int k = 0; k < XD; k += 2) {
    const float2 a0 = *reinterpret_cast<const float2*>(&sa[tr * PAW + k]);
    const float2 a1 = *reinterpret_cast<const float2*>(&sa[(tr + 8) * PAW + k]);
    const float4 w0 = *reinterpret_cast<const float4*>(&sw[k * PWW + tc * 4]);
    const float4 w1 = *reinterpret_cast<const float4*>(&sw[(k + 1) * PWW + tc * 4]);
    acc[0][0] = fmaf(a0.x, w0.x, acc[0][0]); acc[0][1] = fmaf(a0.x, w0.y, acc[0][1]);
    acc[0][2] = fmaf(a0.x, w0.z, acc[0][2]); acc[0][3] = fmaf(a0.x, w0.w, acc[0][3]);
    acc[1][0] = fmaf(a1.x, w0.x, acc[1][0]); acc[1][1] = fmaf(a1.x, w0.y, acc[1][1]);
    acc[1][2] = fmaf(a1.x, w0.z, acc[1][2]); acc[1][3] = fmaf(a1.x, w0.w, acc[1][3]);
    acc[0][0] = fmaf(a0.y, w1.x, acc[0][0]); acc[0][1] = fmaf(a0.y, w1.y, acc[0][1]);
    acc[0][2] = fmaf(a0.y, w1.z, acc[0][2]); acc[0][3] = fmaf(a0.y, w1.w, acc[0][3]);
    acc[1][0] = fmaf(a1.y, w1.x, acc[1][0]); acc[1][1] = fmaf(a1.y, w1.y, acc[1][1]);
    acc[1][2] = fmaf(a1.y, w1.z, acc[1][2]); acc[1][3] = fmaf(a1.y, w1.w, acc[1][3]);
  }

  float* dst = which ? g_ypb : g_xp;
  float4 bias = make_float4(0.f, 0.f, 0.f, 0.f);
  if (which) bias = *reinterpret_cast<const float4*>(&b1[c0 + tc * 4]);
#pragma unroll
  for (int r = 0; r < 2; r++) {
    float4 v = make_float4(acc[r][0] + bias.x, acc[r][1] + bias.y,
                           acc[r][2] + bias.z, acc[r][3] + bias.w);
    *reinterpret_cast<float4*>(&dst[(r0 + tr + 8 * r) * HID + c0 + tc * 4]) = v;
  }
}

// ---------------- main pairwise kernel (R1 config) ----------------
// grid (16 j, 32 i); block 256; microtile 4j x 2i (strided 16); 2 CTAs/SM
__global__ void __launch_bounds__(256, 2) pair_kernel(
    const float* __restrict__ W2, const float* __restrict__ b2)
{
  extern __shared__ float sm[];
  float* sa = sm;                       // TJ rows of xp
  float* sc = sm + TJ * SWID;           // TI rows of ypb
  float* sw = sm + (TJ + TI) * SWID;    // W2 (reused for reductions)

  const int tid = threadIdx.x;
  const int bj = blockIdx.x, bi = blockIdx.y;
  const int jbase = bj * TJ, ibase = bi * TI;

  {
    const float4* src = reinterpret_cast<const float4*>(&g_xp[jbase * HID]);
    for (int t = tid; t < TJ * (HID / 4); t += 256) {
      const int r = t >> 6, c4 = t & 63;
      *reinterpret_cast<float4*>(&sa[r * SWID + c4 * 4]) = src[r * 64 + c4];
    }
  }
  {
    const float4* src = reinterpret_cast<const float4*>(&g_ypb[ibase * HID]);
    for (int t = tid; t < TI * (HID / 4); t += 256) {
      const int r = t >> 6, c4 = t & 63;
      *reinterpret_cast<float4*>(&sc[r * SWID + c4 * 4]) = src[r * 64 + c4];
    }
  }
  sw[tid] = W2[tid];
  __syncthreads();

  const int tx = tid & 15;    // j
  const int ty = tid >> 4;    // i

  unsigned long long acc[8];
#pragma unroll
  for (int p = 0; p < 8; p++) acc[p] = 0ull;

#pragma unroll 4
  for (int k = 0; k < HID; k += 4) {
    const ulonglong2 wv = *reinterpret_cast<const ulonglong2*>(&sw[k]);
    ulonglong2 av[4], cv[2];
#pragma unroll
    for (int jj = 0; jj < 4; jj++)
      av[jj] = *reinterpret_cast<const ulonglong2*>(&sa[(tx + 16 * jj) * SWID + k]);
#pragma unroll
    for (int ii = 0; ii < 2; ii++)
      cv[ii] = *reinterpret_cast<const ulonglong2*>(&sc[(ty + 16 * ii) * SWID + k]);
#pragma unroll
    for (int ii = 0; ii < 2; ii++)
#pragma unroll
      for (int jj = 0; jj < 4; jj++) {
        RELU_DOT(acc[ii * 4 + jj], av[jj].x, cv[ii].x, wv.x);
        RELU_DOT(acc[ii * 4 + jj], av[jj].y, cv[ii].y, wv.y);
      }
  }

  const float b2v = __ldg(b2);
  float eacc = 0.0f, dacc = 0.0f;
#pragma unroll
  for (int ii = 0; ii < 2; ii++)
#pragma unroll
    for (int jj = 0; jj < 4; jj++) {
      union { unsigned long long u; float2 f; } uu;
      uu.u = acc[ii * 4 + jj];
      const float t = uu.f.x + uu.f.y + b2v;
      eacc += __expf(t - 1.0f);
      const int gi = ibase + ty + 16 * ii;
      const int gj = jbase + tx + 16 * jj;
      if (gi == gj) dacc += t;
    }

  __syncthreads();
  sw[tid] = eacc;
  __syncthreads();
  for (int s = 128; s > 0; s >>= 1) {
    if (tid < s) sw[tid] += sw[tid + s];
    __syncthreads();
  }
  if (tid == 0) g_pexp[bi * 16 + bj] = sw[0];
  __syncthreads();
  sw[tid] = dacc;
  __syncthreads();
  for (int s = 128; s > 0; s >>= 1) {
    if (tid < s) sw[tid] += sw[tid + s];
    __syncthreads();
  }
  if (tid == 0) g_pdiag[bi * 16 + bj] = sw[0];
}

// ---------------- finalize ----------------
__global__ void __launch_bounds__(256) finalize_kernel(float* out, int out_size)
{
  __shared__ float se[256];
  __shared__ float sd[256];
  const int tid = threadIdx.x;
  se[tid] = g_pexp[tid] + g_pexp[tid + 256];
  sd[tid] = g_pdiag[tid] + g_pdiag[tid + 256];
  __syncthreads();
  for (int s = 128; s > 0; s >>= 1) {
    if (tid < s) { se[tid] += se[tid + s]; sd[tid] += sd[tid + s]; }
    __syncthreads();
  }
  if (tid == 0)
    out[0] = sd[0] * (1.0f / NPTS) - se[0] * (1.0f / ((float)NPTS * (float)NPTS));
  for (int t = tid; t < out_size; t += 256)
    if (t > 0) out[t] = 0.0f;
}

extern "C" void kernel_launch(void* const* d_in, const int* in_sizes, int n_in,
                              void* d_out, int out_size)
{
  const float* x  = (const float*)d_in[0];
  const float* y  = (const float*)d_in[1];
  const float* W1 = (const float*)d_in[2];
  const float* b1 = (const float*)d_in[3];
  const float* W2 = (const float*)d_in[4];
  const float* b2 = (const float*)d_in[5];

  cudaFuncSetAttribute(pair_kernel, cudaFuncAttributeMaxDynamicSharedMemorySize, SMEM_BYTES);

  prologue_kernel<<<dim3(64, 4, 2), 128>>>(x, y, W1, b1);
  pair_kernel<<<dim3(16, 32), 256, SMEM_BYTES>>>(W2, b2);
  finalize_kernel<<<1, 256>>>((float*)d_out, out_size);
}

// round 8
// speedup vs baseline: 1.8531x; 1.1424x over previous
#include <cuda_runtime.h>

#define NPTS 1024
#define HID  256
#define XD   128

// ---------------- pair kernel tiling: 64x64 tile, k-chunked x2 ----------------
#define TJ   64
#define TI   64
#define KC   128                 // k-chunk width
#define SWID 132                 // chunk row stride (floats)
#define SMEM_BYTES (((TJ + TI) * SWID + 256 + 16) * 4)   // ~68.7KB -> 2 CTAs/SM

// ---------------- prologue tiling: 16r x 32c, 1024 blocks ----------------
#define PR   16
#define PC   32
#define PAW  132                 // a-row stride
#define PWW  36                  // w-row stride (floats)

// ---- device scratch ----
__device__ float g_xp [NPTS * HID];
__device__ float g_ypb[NPTS * HID];
__device__ float g_pexp [256];
__device__ float g_pdiag[256];

// packed f32x2 relu-dot: acc += relu(a + c) * w  (2 elems; movs are reg-renamed away)
#define RELU_DOT(ACC, A, C, W)                         \
  asm("{\n\t"                                          \
      ".reg .b64 zz, rr;\n\t"                          \
      ".reg .f32 zl, zh, rl, rh;\n\t"                  \
      "add.rn.f32x2 zz, %1, %2;\n\t"                   \
      "mov.b64 {zl, zh}, zz;\n\t"                      \
      "max.f32 rl, zl, 0f00000000;\n\t"                \
      "max.f32 rh, zh, 0f00000000;\n\t"                \
      "mov.b64 rr, {rl, rh};\n\t"                      \
      "fma.rn.f32x2 %0, rr, %3, %0;\n\t"               \
      "}" : "+l"(ACC) : "l"(A), "l"(C), "l"(W))

// ---------------- prologue: xp = x @ W1[:128], ypb = y @ W1[128:] + b1 ----------------
// block 128 thr; tile 16r x 32c; microtile 1r x 4c; grid (64, 8, 2) = 1024 blocks (single wave).
__global__ void __launch_bounds__(128, 8) prologue_kernel(
    const float* __restrict__ x, const float* __restrict__ y,
    const float* __restrict__ W1, const float* __restrict__ b1)
{
  __shared__ float sa[PR * PAW];     // [r][k]  16 x 132
  __shared__ float sw[XD * PWW];     // [k][c] 128 x 36

  const int which = blockIdx.z;
  const float* src = which ? y : x;
  const int r0 = blockIdx.x * PR;
  const int c0 = blockIdx.y * PC;
  const int tid = threadIdx.x;

  // stage a: 16 rows x 128 k
  for (int t = tid; t < PR * (XD / 4); t += 128) {
    const int r = t >> 5, k4 = t & 31;
    *reinterpret_cast<float4*>(&sa[r * PAW + k4 * 4]) =
        *reinterpret_cast<const float4*>(&src[(r0 + r) * XD + k4 * 4]);
  }
  // stage w: 128 k x 32 c
  const float* Wb = W1 + (which ? (XD * HID) : 0) + c0;
  for (int t = tid; t < XD * (PC / 4); t += 128) {
    const int k = t >> 3, c4 = t & 7;
    *reinterpret_cast<float4*>(&sw[k * PWW + c4 * 4]) =
        *reinterpret_cast<const float4*>(&Wb[k * HID + c4 * 4]);
  }
  __syncthreads();

  const int tc = tid & 7;     // col quad: cols 4*tc..4*tc+3
  const int tr = tid >> 3;    // row 0..15

  float a0 = 0.f, a1 = 0.f, a2 = 0.f, a3 = 0.f;

#pragma unroll 4
  for (int k = 0; k < XD; k += 2) {
    const float2 av = *reinterpret_cast<const float2*>(&sa[tr * PAW + k]);
    const float4 w0 = *reinterpret_cast<const float4*>(&sw[k * PWW + tc * 4]);
    const float4 w1 = *reinterpret_cast<const float4*>(&sw[(k + 1) * PWW + tc * 4]);
    a0 = fmaf(av.x, w0.x, a0); a1 = fmaf(av.x, w0.y, a1);
    a2 = fmaf(av.x, w0.z, a2); a3 = fmaf(av.x, w0.w, a3);
    a0 = fmaf(av.y, w1.x, a0); a1 = fmaf(av.y, w1.y, a1);
    a2 = fmaf(av.y, w1.z, a2); a3 = fmaf(av.y, w1.w, a3);
  }

  float* dst = which ? g_ypb : g_xp;
  float4 bias = make_float4(0.f, 0.f, 0.f, 0.f);
  if (which) bias = *reinterpret_cast<const float4*>(&b1[c0 + tc * 4]);
  float4 v = make_float4(a0 + bias.x, a1 + bias.y, a2 + bias.z, a3 + bias.w);
  *reinterpret_cast<float4*>(&dst[(r0 + tr) * HID + c0 + tc * 4]) = v;
}

// ---------------- main pairwise kernel ----------------
// grid (16 j, 16 i) = 256 blocks; block 256; 2 CTAs/SM; microtile 4j x 4i; k chunked x2
__global__ void __launch_bounds__(256, 2) pair_kernel(
    const float* __restrict__ W2, const float* __restrict__ b2)
{
  extern __shared__ float sm[];
  float* sa = sm;                       // TJ x SWID (xp chunk)
  float* sc = sm + TJ * SWID;           // TI x SWID (ypb chunk)
  float* sw = sm + (TJ + TI) * SWID;    // 256 W2 (reused for reductions)

  const int tid = threadIdx.x;
  const int bj = blockIdx.x, bi = blockIdx.y;
  const int jbase = bj * TJ, ibase = bi * TI;

  sw[tid] = W2[tid];

  const int tx = tid & 15;    // j group: rows tx + 16*jj
  const int ty = tid >> 4;    // i group: rows ty + 16*ii

  unsigned long long acc[16];
#pragma unroll
  for (int p = 0; p < 16; p++) acc[p] = 0ull;

  for (int kc = 0; kc < 2; kc++) {
    __syncthreads();            // protect previous chunk reads before overwrite
    {
      const float4* src = reinterpret_cast<const float4*>(&g_xp[jbase * HID + kc * KC]);
      for (int t = tid; t < TJ * (KC / 4); t += 256) {
        const int r = t >> 5, c4 = t & 31;
        // row stride in src is HID/4 = 64 float4
        *reinterpret_cast<float4*>(&sa[r * SWID + c4 * 4]) = src[r * 64 + c4];
      }
      const float4* src2 = reinterpret_cast<const float4*>(&g_ypb[ibase * HID + kc * KC]);
      for (int t = tid; t < TI * (KC / 4); t += 256) {
        const int r = t >> 5, c4 = t & 31;
        *reinterpret_cast<float4*>(&sc[r * SWID + c4 * 4]) = src2[r * 64 + c4];
      }
    }
    __syncthreads();

    const float* swk = sw + kc * KC;
#pragma unroll 2
    for (int k = 0; k < KC; k += 4) {
      const ulonglong2 wv = *reinterpret_cast<const ulonglong2*>(&swk[k]);
      ulonglong2 av[4], cv[4];
#pragma unroll
      for (int jj = 0; jj < 4; jj++)
        av[jj] = *reinterpret_cast<const ulonglong2*>(&sa[(tx + 16 * jj) * SWID + k]);
#pragma unroll
      for (int ii = 0; ii < 4; ii++)
        cv[ii] = *reinterpret_cast<const ulonglong2*>(&sc[(ty + 16 * ii) * SWID + k]);
#pragma unroll
      for (int ii = 0; ii < 4; ii++)
#pragma unroll
        for (int jj = 0; jj < 4; jj++) {
          RELU_DOT(acc[ii * 4 + jj], av[jj].x, cv[ii].x, wv.x);
          RELU_DOT(acc[ii * 4 + jj], av[jj].y, cv[ii].y, wv.y);
        }
    }
  }

  const float b2v = __ldg(b2);
  float eacc = 0.0f, dacc = 0.0f;
#pragma unroll
  for (int ii = 0; ii < 4; ii++)
#pragma unroll
    for (int jj = 0; jj < 4; jj++) {
      union { unsigned long long u; float2 f; } uu;
      uu.u = acc[ii * 4 + jj];
      const float t = uu.f.x + uu.f.y + b2v;
      eacc += __expf(t - 1.0f);
      const int gi = ibase + ty + 16 * ii;
      const int gj = jbase + tx + 16 * jj;
      if (gi == gj) dacc += t;
    }

  __syncthreads();
  sw[tid] = eacc;
  __syncthreads();
  for (int s = 128; s > 0; s >>= 1) {
    if (tid < s) sw[tid] += sw[tid + s];
    __syncthreads();
  }
  if (tid == 0) g_pexp[bi * 16 + bj] = sw[0];
  __syncthreads();
  sw[tid] = dacc;
  __syncthreads();
  for (int s = 128; s > 0; s >>= 1) {
    if (tid < s) sw[tid] += sw[tid + s];
    __syncthreads();
  }
  if (tid == 0) g_pdiag[bi * 16 + bj] = sw[0];
}

// ---------------- finalize ----------------
__global__ void __launch_bounds__(256) finalize_kernel(float* out, int out_size)
{
  __shared__ float se[256];
  __shared__ float sd[256];
  const int tid = threadIdx.x;
  se[tid] = g_pexp[tid];
  sd[tid] = g_pdiag[tid];
  __syncthreads();
  for (int s = 128; s > 0; s >>= 1) {
    if (tid < s) { se[tid] += se[tid + s]; sd[tid] += sd[tid + s]; }
    __syncthreads();
  }
  if (tid == 0)
    out[0] = sd[0] * (1.0f / NPTS) - se[0] * (1.0f / ((float)NPTS * (float)NPTS));
  for (int t = tid; t < out_size; t += 256)
    if (t > 0) out[t] = 0.0f;
}

extern "C" void kernel_launch(void* const* d_in, const int* in_sizes, int n_in,
                              void* d_out, int out_size)
{
  const float* x  = (const float*)d_in[0];
  const float* y  = (const float*)d_in[1];
  const float* W1 = (const float*)d_in[2];
  const float* b1 = (const float*)d_in[3];
  const float* W2 = (const float*)d_in[4];
  const float* b2 = (const float*)d_in[5];

  cudaFuncSetAttribute(pair_kernel, cudaFuncAttributeMaxDynamicSharedMemorySize, SMEM_BYTES);

  prologue_kernel<<<dim3(64, 8, 2), 128>>>(x, y, W1, b1);
  pair_kernel<<<dim3(16, 16), 256, SMEM_BYTES>>>(W2, b2);
  finalize_kernel<<<1, 256>>>((float*)d_out, out_size);
}

// round 10
// speedup vs baseline: 1.9038x; 1.0274x over previous
#include <cuda_runtime.h>

#define NPTS 1024
#define HID  256
#define XD   128

// ---------------- pair kernel tiling: 64x64 tile, k-chunked x2 ----------------
#define TJ   64
#define TI   64
#define KC   128
#define SWID 132
#define SMEM_BYTES (((TJ + TI) * SWID + 256 + 16) * 4)   // ~68.7KB -> 2 CTAs/SM

// ---- device scratch ----
__device__ float g_xp [NPTS * HID];
__device__ float g_ypb[NPTS * HID];
__device__ float g_pexp [256];
__device__ float g_pdiag[256];
__device__ unsigned int g_count = 0;

// packed f32x2 relu-dot: acc += relu(a + c) * w  (2 elems)
#define RELU_DOT(ACC, A, C, W)                         \
  asm("{\n\t"                                          \
      ".reg .b64 zz, rr;\n\t"                          \
      ".reg .f32 zl, zh, rl, rh;\n\t"                  \
      "add.rn.f32x2 zz, %1, %2;\n\t"                   \
      "mov.b64 {zl, zh}, zz;\n\t"                      \
      "max.f32 rl, zl, 0f00000000;\n\t"                \
      "max.f32 rh, zh, 0f00000000;\n\t"                \
      "mov.b64 rr, {rl, rh};\n\t"                      \
      "fma.rn.f32x2 %0, rr, %3, %0;\n\t"               \
      "}" : "+l"(ACC) : "l"(A), "l"(C), "l"(W))

// ---------------- prologue: LDG-direct, no smem, no syncs ----------------
// block 128 thr = 4 warps. Warp: 2 rows x 128 cols; thread: 2 rows x 4 cols.
// grid (128 rowgroups, 2 colhalves, 2 which) = 512 blocks.
// W1 is L2-resident (128KB); x row loads are warp-uniform (1 sector, L1-hit).
__global__ void __launch_bounds__(128) prologue_kernel(
    const float* __restrict__ x, const float* __restrict__ y,
    const float* __restrict__ W1, const float* __restrict__ b1)
{
  const int which = blockIdx.z;
  const int lane  = threadIdx.x & 31;
  const int warp  = threadIdx.x >> 5;
  const int r0    = blockIdx.x * 8 + warp * 2;
  const int c     = blockIdx.y * 128 + lane * 4;

  const float* __restrict__ A  = (which ? y : x) + r0 * XD;
  const float* __restrict__ Wp = W1 + (which ? (XD * HID) : 0) + c;

  float acc0[4] = {0.f, 0.f, 0.f, 0.f};
  float acc1[4] = {0.f, 0.f, 0.f, 0.f};

#pragma unroll 2
  for (int k = 0; k < XD; k += 4) {
    const float4 a0 = *reinterpret_cast<const float4*>(&A[k]);
    const float4 a1 = *reinterpret_cast<const float4*>(&A[XD + k]);
    float4 w[4];
#pragma unroll
    for (int i = 0; i < 4; i++)
      w[i] = *reinterpret_cast<const float4*>(&Wp[(k + i) * HID]);

    acc0[0] = fmaf(a0.x, w[0].x, acc0[0]); acc0[1] = fmaf(a0.x, w[0].y, acc0[1]);
    acc0[2] = fmaf(a0.x, w[0].z, acc0[2]); acc0[3] = fmaf(a0.x, w[0].w, acc0[3]);
    acc1[0] = fmaf(a1.x, w[0].x, acc1[0]); acc1[1] = fmaf(a1.x, w[0].y, acc1[1]);
    acc1[2] = fmaf(a1.x, w[0].z, acc1[2]); acc1[3] = fmaf(a1.x, w[0].w, acc1[3]);

    acc0[0] = fmaf(a0.y, w[1].x, acc0[0]); acc0[1] = fmaf(a0.y, w[1].y, acc0[1]);
    acc0[2] = fmaf(a0.y, w[1].z, acc0[2]); acc0[3] = fmaf(a0.y, w[1].w, acc0[3]);
    acc1[0] = fmaf(a1.y, w[1].x, acc1[0]); acc1[1] = fmaf(a1.y, w[1].y, acc1[1]);
    acc1[2] = fmaf(a1.y, w[1].z, acc1[2]); acc1[3] = fmaf(a1.y, w[1].w, acc1[3]);

    acc0[0] = fmaf(a0.z, w[2].x, acc0[0]); acc0[1] = fmaf(a0.z, w[2].y, acc0[1]);
    acc0[2] = fmaf(a0.z, w[2].z, acc0[2]); acc0[3] = fmaf(a0.z, w[2].w, acc0[3]);
    acc1[0] = fmaf(a1.z, w[2].x, acc1[0]); acc1[1] = fmaf(a1.z, w[2].y, acc1[1]);
    acc1[2] = fmaf(a1.z, w[2].z, acc1[2]); acc1[3] = fmaf(a1.z, w[2].w, acc1[3]);

    acc0[0] = fmaf(a0.w, w[3].x, acc0[0]); acc0[1] = fmaf(a0.w, w[3].y, acc0[1]);
    acc0[2] = fmaf(a0.w, w[3].z, acc0[2]); acc0[3] = fmaf(a0.w, w[3].w, acc0[3]);
    acc1[0] = fmaf(a1.w, w[3].x, acc1[0]); acc1[1] = fmaf(a1.w, w[3].y, acc1[1]);
    acc1[2] = fmaf(a1.w, w[3].z, acc1[2]); acc1[3] = fmaf(a1.w, w[3].w, acc1[3]);
  }

  float4 bias = make_float4(0.f, 0.f, 0.f, 0.f);
  if (which) bias = *reinterpret_cast<const float4*>(&b1[c]);

  float* dst = which ? g_ypb : g_xp;
  float4 v0 = make_float4(acc0[0] + bias.x, acc0[1] + bias.y,
                          acc0[2] + bias.z, acc0[3] + bias.w);
  float4 v1 = make_float4(acc1[0] + bias.x, acc1[1] + bias.y,
                          acc1[2] + bias.z, acc1[3] + bias.w);
  *reinterpret_cast<float4*>(&dst[(r0 + 0) * HID + c]) = v0;
  *reinterpret_cast<float4*>(&dst[(r0 + 1) * HID + c]) = v1;
}

// ---------------- main pairwise kernel (finalize fused: last block reduces) ----------------
// grid (16 j, 16 i) = 256 blocks; block 256; 2 CTAs/SM; microtile 4j x 4i; k chunked x2
__global__ void __launch_bounds__(256, 2) pair_kernel(
    const float* __restrict__ W2, const float* __restrict__ b2,
    float* __restrict__ out, int out_size)
{
  extern __shared__ float sm[];
  float* sa = sm;                       // TJ x SWID (xp chunk)
  float* sc = sm + TJ * SWID;           // TI x SWID (ypb chunk)
  float* sw = sm + (TJ + TI) * SWID;    // 256 W2 (reused for reductions)

  const int tid = threadIdx.x;
  const int bj = blockIdx.x, bi = blockIdx.y;
  const int jbase = bj * TJ, ibase = bi * TI;

  sw[tid] = W2[tid];

  const int tx = tid & 15;    // j group: rows tx + 16*jj
  const int ty = tid >> 4;    // i group: rows ty + 16*ii

  unsigned long long acc[16];
#pragma unroll
  for (int p = 0; p < 16; p++) acc[p] = 0ull;

  for (int kc = 0; kc < 2; kc++) {
    __syncthreads();
    {
      const float4* src = reinterpret_cast<const float4*>(&g_xp[jbase * HID + kc * KC]);
      for (int t = tid; t < TJ * (KC / 4); t += 256) {
        const int r = t >> 5, c4 = t & 31;
        *reinterpret_cast<float4*>(&sa[r * SWID + c4 * 4]) = src[r * 64 + c4];
      }
      const float4* src2 = reinterpret_cast<const float4*>(&g_ypb[ibase * HID + kc * KC]);
      for (int t = tid; t < TI * (KC / 4); t += 256) {
        const int r = t >> 5, c4 = t & 31;
        *reinterpret_cast<float4*>(&sc[r * SWID + c4 * 4]) = src2[r * 64 + c4];
      }
    }
    __syncthreads();

    const float* swk = sw + kc * KC;
#pragma unroll 2
    for (int k = 0; k < KC; k += 4) {
      const ulonglong2 wv = *reinterpret_cast<const ulonglong2*>(&swk[k]);
      ulonglong2 av[4], cv[4];
#pragma unroll
      for (int jj = 0; jj < 4; jj++)
        av[jj] = *reinterpret_cast<const ulonglong2*>(&sa[(tx + 16 * jj) * SWID + k]);
#pragma unroll
      for (int ii = 0; ii < 4; ii++)
        cv[ii] = *reinterpret_cast<const ulonglong2*>(&sc[(ty + 16 * ii) * SWID + k]);
#pragma unroll
      for (int ii = 0; ii < 4; ii++)
#pragma unroll
        for (int jj = 0; jj < 4; jj++) {
          RELU_DOT(acc[ii * 4 + jj], av[jj].x, cv[ii].x, wv.x);
          RELU_DOT(acc[ii * 4 + jj], av[jj].y, cv[ii].y, wv.y);
        }
    }
  }

  const float b2v = __ldg(b2);
  float eacc = 0.0f, dacc = 0.0f;
#pragma unroll
  for (int ii = 0; ii < 4; ii++)
#pragma unroll
    for (int jj = 0; jj < 4; jj++) {
      union { unsigned long long u; float2 f; } uu;
      uu.u = acc[ii * 4 + jj];
      const float t = uu.f.x + uu.f.y + b2v;
      eacc += __expf(t - 1.0f);
      const int gi = ibase + ty + 16 * ii;
      const int gj = jbase + tx + 16 * jj;
      if (gi == gj) dacc += t;
    }

  __syncthreads();
  sw[tid] = eacc;
  __syncthreads();
  for (int s = 128; s > 0; s >>= 1) {
    if (tid < s) sw[tid] += sw[tid + s];
    __syncthreads();
  }
  if (tid == 0) g_pexp[bi * 16 + bj] = sw[0];
  __syncthreads();
  sw[tid] = dacc;
  __syncthreads();
  for (int s = 128; s > 0; s >>= 1) {
    if (tid < s) sw[tid] += sw[tid + s];
    __syncthreads();
  }
  if (tid == 0) g_pdiag[bi * 16 + bj] = sw[0];

  // ---- fused finalize: last block to finish reduces the 256 partials ----
  __threadfence();
  __shared__ int lastflag;
  if (tid == 0) {
    const unsigned int old = atomicAdd(&g_count, 1u);
    lastflag = (old == 255u);
  }
  __syncthreads();
  if (lastflag) {
    __threadfence();
    __shared__ float esum_s;
    sw[tid] = g_pexp[tid];
    __syncthreads();
    for (int s = 128; s > 0; s >>= 1) {
      if (tid < s) sw[tid] += sw[tid + s];
      __syncthreads();
    }
    if (tid == 0) esum_s = sw[0];
    __syncthreads();
    sw[tid] = g_pdiag[tid];
    __syncthreads();
    for (int s = 128; s > 0; s >>= 1) {
      if (tid < s) sw[tid] += sw[tid + s];
      __syncthreads();
    }
    if (tid == 0) {
      out[0] = sw[0] * (1.0f / NPTS) - esum_s * (1.0f / ((float)NPTS * (float)NPTS));
      g_count = 0u;   // self-reset for next graph replay
    }
    for (int t = tid; t < out_size; t += 256)
      if (t > 0) out[t] = 0.0f;
  }
}

extern "C" void kernel_launch(void* const* d_in, const int* in_sizes, int n_in,
                              void* d_out, int out_size)
{
  const float* x  = (const float*)d_in[0];
  const float* y  = (const float*)d_in[1];
  const float* W1 = (const float*)d_in[2];
  const float* b1 = (const float*)d_in[3];
  const float* W2 = (const float*)d_in[4];
  const float* b2 = (const float*)d_in[5];

  cudaFuncSetAttribute(pair_kernel, cudaFuncAttributeMaxDynamicSharedMemorySize, SMEM_BYTES);

  prologue_kernel<<<dim3(128, 2, 2), 128>>>(x, y, W1, b1);
  pair_kernel<<<dim3(16, 16), 256, SMEM_BYTES>>>(W2, b2, (float*)d_out, out_size);
}